// round 2
// baseline (speedup 1.0000x reference)
#include <cuda_runtime.h>
#include <cstdint>

// FPSampler: farthest point sampling, B=16, N=131072, npoint=1024.
// 16 clusters x 8 CTAs, 512 threads/CTA, one CTA per SM (single wave).
// xyz planes resident in 192KB SMEM per CTA, distances in registers.
// Per-group winner exchange via DSMEM all-to-all + cluster barrier.

#define BB 16
#define NN 131072
#define NP 1024
#define GG 8                     // CTAs per cluster (batch group)
#define PTS (NN / GG)            // 16384 points per CTA
#define NT 512                   // threads per CTA
#define JJ 8                     // float4 chunks per thread (8*4 = 32 points)
#define GRID (BB * GG)           // 128 CTAs
#define SMEM_BYTES (3 * PTS * sizeof(float))

struct StartArg { int s[BB]; };

// ---------------- packed f32x2 helpers (exact per-element rn ops) -----------
__device__ __forceinline__ unsigned long long f2add(unsigned long long a,
                                                    unsigned long long b) {
    unsigned long long r;
    asm("add.rn.f32x2 %0, %1, %2;" : "=l"(r) : "l"(a), "l"(b));
    return r;
}
__device__ __forceinline__ unsigned long long f2mul(unsigned long long a,
                                                    unsigned long long b) {
    unsigned long long r;
    asm("mul.rn.f32x2 %0, %1, %2;" : "=l"(r) : "l"(a), "l"(b));
    return r;
}
__device__ __forceinline__ unsigned long long pack2(float a, float b) {
    unsigned long long r;
    asm("mov.b64 %0, {%1, %2};" : "=l"(r) : "f"(a), "f"(b));
    return r;
}
__device__ __forceinline__ void unpack2(unsigned long long v, float& a, float& b) {
    asm("mov.b64 {%0, %1}, %2;" : "=f"(a), "=f"(b) : "l"(v));
}

// ---------------- DSMEM stores --------------------------------------------
__device__ __forceinline__ uint32_t smem_u32(const void* p) {
    uint32_t a;
    asm("{ .reg .u64 t; cvta.to.shared.u64 t, %1; cvt.u32.u64 %0, t; }"
        : "=r"(a) : "l"(p));
    return a;
}
__device__ __forceinline__ void st_cluster_u64(uint32_t laddr, uint32_t rank,
                                               unsigned long long v) {
    uint32_t r;
    asm volatile("mapa.shared::cluster.u32 %0, %1, %2;" : "=r"(r) : "r"(laddr), "r"(rank));
    asm volatile("st.shared::cluster.b64 [%0], %1;" :: "r"(r), "l"(v) : "memory");
}
__device__ __forceinline__ void st_cluster_u32(uint32_t laddr, uint32_t rank,
                                               uint32_t v) {
    uint32_t r;
    asm volatile("mapa.shared::cluster.u32 %0, %1, %2;" : "=r"(r) : "r"(laddr), "r"(rank));
    asm volatile("st.shared::cluster.b32 [%0], %1;" :: "r"(r), "r"(v) : "memory");
}

__global__ void __launch_bounds__(NT, 1) __cluster_dims__(GG, 1, 1)
fps_main_kernel(const float* __restrict__ xyz, float* __restrict__ out, StartArg st)
{
    extern __shared__ float smem[];
    float* xs = smem;
    float* ys = smem + PTS;
    float* zs = smem + 2 * PTS;
    const float4* xs4 = (const float4*)xs;
    const float4* ys4 = (const float4*)ys;
    const float4* zs4 = (const float4*)zs;

    __shared__ unsigned long long wred[NT / 32];
    __shared__ unsigned long long slot_pk[2][GG];
    __shared__ unsigned long long slot_xy[2][GG];
    __shared__ float              slot_z [2][GG];

    const int cta  = blockIdx.x;
    const int b    = cta >> 3;       // batch (GG == 8)
    const int c    = cta & 7;        // rank within cluster
    const int t    = threadIdx.x;
    const int lane = t & 31;
    const int warp = t >> 5;
    const int base = c * PTS;        // first global point index of this CTA

    const float* xb = xyz + (size_t)b * NN * 3;
    float* out_xyz = out;
    float* out_idx = out + (size_t)BB * NP * 3;

    // One-time load of this CTA's point slab into SMEM planes.
    for (int p = t; p < PTS; p += NT) {
        const float* src = xb + (size_t)(base + p) * 3;
        xs[p] = src[0];
        ys[p] = src[1];
        zs[p] = src[2];
    }

    float dist[JJ][4];
#pragma unroll
    for (int j = 0; j < JJ; j++)
#pragma unroll
        for (int e = 0; e < 4; e++) dist[j][e] = 1e10f;   // INF from reference

    // First centroid = start[b].
    const int fi = st.s[b];
    float cx = xb[(size_t)fi * 3 + 0];
    float cy = xb[(size_t)fi * 3 + 1];
    float cz = xb[(size_t)fi * 3 + 2];

    if (c == 0 && t == 0) {
        size_t o3 = (size_t)b * NP * 3;
        out_xyz[o3 + 0] = cx;
        out_xyz[o3 + 1] = cy;
        out_xyz[o3 + 2] = cz;
        out_idx[(size_t)b * NP] = (float)fi;
    }
    __syncthreads();

    const uint32_t spk = smem_u32(&slot_pk[0][0]);
    const uint32_t sxy = smem_u32(&slot_xy[0][0]);
    const uint32_t sz  = smem_u32(&slot_z [0][0]);

    for (int it = 1; it < NP; it++) {
        const int buf = it & 1;
        // packed negated centroid (x - c == x + (-c) exactly)
        const unsigned long long ncx2 = pack2(-cx, -cx);
        const unsigned long long ncy2 = pack2(-cy, -cy);
        const unsigned long long ncz2 = pack2(-cz, -cz);

        // ---- distance update + local argmax (first-index semantics) ----
        float bestv = -1.0f;
        int bestp = 0;
#pragma unroll
        for (int j = 0; j < JJ; j++) {
            const int c0 = j * NT + t;            // chunk index; points 4c0..4c0+3
            float4 x4 = xs4[c0];
            float4 y4 = ys4[c0];
            float4 z4 = zs4[c0];

            unsigned long long dxa = f2add(pack2(x4.x, x4.y), ncx2);
            unsigned long long dxb = f2add(pack2(x4.z, x4.w), ncx2);
            unsigned long long dya = f2add(pack2(y4.x, y4.y), ncy2);
            unsigned long long dyb = f2add(pack2(y4.z, y4.w), ncy2);
            unsigned long long dza = f2add(pack2(z4.x, z4.y), ncz2);
            unsigned long long dzb = f2add(pack2(z4.z, z4.w), ncz2);
            // exact reference order: (dx*dx + dy*dy) + dz*dz
            unsigned long long sa =
                f2add(f2add(f2mul(dxa, dxa), f2mul(dya, dya)), f2mul(dza, dza));
            unsigned long long sb =
                f2add(f2add(f2mul(dxb, dxb), f2mul(dyb, dyb)), f2mul(dzb, dzb));

            float d0, d1, d2, d3;
            unpack2(sa, d0, d1);
            unpack2(sb, d2, d3);

            float nd;
            nd = fminf(dist[j][0], d0); dist[j][0] = nd;
            if (nd > bestv) { bestv = nd; bestp = 4 * c0 + 0; }
            nd = fminf(dist[j][1], d1); dist[j][1] = nd;
            if (nd > bestv) { bestv = nd; bestp = 4 * c0 + 1; }
            nd = fminf(dist[j][2], d2); dist[j][2] = nd;
            if (nd > bestv) { bestv = nd; bestp = 4 * c0 + 2; }
            nd = fminf(dist[j][3], d3); dist[j][3] = nd;
            if (nd > bestv) { bestv = nd; bestp = 4 * c0 + 3; }
        }
        // distances >= 0 -> float bits monotone as unsigned; ~idx => tie -> low idx
        unsigned gidx = (unsigned)(base + bestp);
        unsigned long long pk =
            ((unsigned long long)__float_as_uint(bestv) << 32) |
            (unsigned)(0xFFFFFFFFu - gidx);

        // ---- warp reduce (bfly max) ----
#pragma unroll
        for (int off = 16; off > 0; off >>= 1) {
            unsigned long long o = __shfl_xor_sync(0xFFFFFFFFu, pk, off);
            if (o > pk) pk = o;
        }
        if (lane == 0) wred[warp] = pk;
        __syncthreads();

        // ---- CTA reduce + DSMEM publish (warp 0) ----
        if (warp == 0) {
            unsigned long long p2 = (lane < (NT / 32)) ? wred[lane] : 0ull;
#pragma unroll
            for (int off = 8; off > 0; off >>= 1) {
                unsigned long long o = __shfl_xor_sync(0xFFFFFFFFu, p2, off);
                if (o > p2) p2 = o;
            }
            if (lane < GG) {                      // lanes 0..7: one peer rank each
                unsigned gw = 0xFFFFFFFFu - (unsigned)(p2 & 0xFFFFFFFFull);
                int lp = (int)gw - base;          // CTA-local winner
                unsigned long long xy = pack2(xs[lp], ys[lp]);
                float wz = zs[lp];
                uint32_t o8 = (uint32_t)((buf * GG + c) * 8);
                uint32_t o4 = (uint32_t)((buf * GG + c) * 4);
                st_cluster_u64(spk + o8, (uint32_t)lane, p2);
                st_cluster_u64(sxy + o8, (uint32_t)lane, xy);
                st_cluster_u32(sz  + o4, (uint32_t)lane, __float_as_uint(wz));
            }
        }

        // cluster-wide barrier: orders DSMEM stores, subsumes __syncthreads
        asm volatile("barrier.cluster.arrive.aligned;" ::: "memory");
        asm volatile("barrier.cluster.wait.aligned;"   ::: "memory");

        // ---- every thread picks the group winner from its local copies ----
        unsigned long long wb = 0ull; int wc = 0;
#pragma unroll
        for (int jj = 0; jj < GG; jj++) {
            unsigned long long v = slot_pk[buf][jj];
            if (v > wb) { wb = v; wc = jj; }
        }
        unpack2(slot_xy[buf][wc], cx, cy);
        cz = slot_z[buf][wc];

        if (c == 0 && t == 0) {
            unsigned widx = 0xFFFFFFFFu - (unsigned)(wb & 0xFFFFFFFFull);
            size_t o3 = ((size_t)b * NP + it) * 3;
            out_xyz[o3 + 0] = cx;
            out_xyz[o3 + 1] = cy;
            out_xyz[o3 + 2] = cz;
            out_idx[(size_t)b * NP + it] = (float)widx;
        }
    }
}

// ---------------------------------------------------------------------------
// Host-side reproduction of JAX Threefry RNG for `start` (verified exact R1):
//   start = randint(fold_in(key(0), 1), (16,), 0, 131072), partitionable mode.
// ---------------------------------------------------------------------------
static void tf2x32(uint32_t k0, uint32_t k1, uint32_t c0, uint32_t c1,
                   uint32_t* o0, uint32_t* o1)
{
    uint32_t ks[3] = { k0, k1, k0 ^ k1 ^ 0x1BD11BDAu };
    uint32_t x0 = c0 + ks[0];
    uint32_t x1 = c1 + ks[1];
    static const int rot[2][4] = { {13, 15, 26, 6}, {17, 29, 16, 24} };
    for (int i = 0; i < 5; i++) {
        const int* r = rot[i & 1];
        for (int j = 0; j < 4; j++) {
            x0 += x1;
            x1 = (x1 << r[j]) | (x1 >> (32 - r[j]));
            x1 ^= x0;
        }
        x0 += ks[(i + 1) % 3];
        x1 += ks[(i + 2) % 3] + (uint32_t)(i + 1);
    }
    *o0 = x0;
    *o1 = x1;
}

static void compute_start(int* s)
{
    uint32_t K0, K1;
    tf2x32(0u, 0u, 0u, 1u, &K0, &K1);       // fold_in(key(0), 1)
    uint32_t b0, b1;
    tf2x32(K0, K1, 0u, 1u, &b0, &b1);       // partitionable split, lower key
    for (int i = 0; i < BB; i++) {
        uint32_t y0, y1;
        tf2x32(b0, b1, 0u, (uint32_t)i, &y0, &y1);
        s[i] = (int)((y0 ^ y1) & (uint32_t)(NN - 1));   // span = 2^17
    }
}

extern "C" void kernel_launch(void* const* d_in, const int* in_sizes, int n_in,
                              void* d_out, int out_size)
{
    const float* xyz = (const float*)d_in[0];
    float* out = (float*)d_out;

    StartArg st;
    compute_start(st.s);

    cudaFuncSetAttribute(fps_main_kernel,
                         cudaFuncAttributeMaxDynamicSharedMemorySize,
                         (int)SMEM_BYTES);

    fps_main_kernel<<<GRID, NT, SMEM_BYTES>>>(xyz, out, st);
}